// round 8
// baseline (speedup 1.0000x reference)
#include <cuda_runtime.h>
#include <cuda_bf16.h>
#include <mma.h>
#include <math.h>
#include <stdint.h>

using namespace nvcuda;

// ---------------------------------------------------------------------------
// DenseGAT: 2-layer GAT, N=100000 nodes, E=1600000 edges, 256 -> 64 -> 40
// bf16-split WMMA (HMMA) GEMM + fused logits; CSR-by-dst; round-4 gather agg.
// ---------------------------------------------------------------------------

#define MAX_NODES 100000
#define MAX_EDGES 1600000
#define SCAN_CHUNK 512
#define MAX_BLOCKS_SCAN 256

__device__ float g_z   [MAX_NODES * 64];
__device__ float g_h   [MAX_NODES * 64];
__device__ float g_el  [MAX_NODES];
__device__ float g_er  [MAX_NODES];
__device__ int   g_deg [MAX_NODES];
__device__ int   g_scan[MAX_NODES];
__device__ int   g_off [MAX_NODES + 1];
__device__ int   g_cur [MAX_NODES];
__device__ int   g_srcs[MAX_EDGES];
__device__ int   g_bsum[MAX_BLOCKS_SCAN];
__device__ int   g_boff[MAX_BLOCKS_SCAN];

// bf16 hi/lo W planes, row-major padded: layer1 [256][64], layer2 [64][48]
__device__ __align__(16) __nv_bfloat16 g_bt1h[256 * 64];
__device__ __align__(16) __nv_bfloat16 g_bt1l[256 * 64];
__device__ __align__(16) __nv_bfloat16 g_bt2h[64 * 48];
__device__ __align__(16) __nv_bfloat16 g_bt2l[64 * 48];

__device__ __forceinline__ float warp_max(float v) {
#pragma unroll
    for (int o = 16; o > 0; o >>= 1)
        v = fmaxf(v, __shfl_xor_sync(0xffffffffu, v, o));
    return v;
}
__device__ __forceinline__ float warp_sum(float v) {
#pragma unroll
    for (int o = 16; o > 0; o >>= 1)
        v += __shfl_xor_sync(0xffffffffu, v, o);
    return v;
}

// ----------------------------- W convert ----------------------------------
// W [K,NOUT] fp32 -> bf16 hi/lo planes [K][NPAD] row-major (cols >= NOUT = 0).

__global__ void wconv_kernel(const float* __restrict__ W, int K, int NOUT, int NPAD,
                             __nv_bfloat16* __restrict__ oh, __nv_bfloat16* __restrict__ ol) {
    int idx = blockIdx.x * blockDim.x + threadIdx.x;
    if (idx >= K * NPAD) return;
    int k = idx / NPAD;
    int n = idx % NPAD;
    float v = (n < NOUT) ? W[k * NOUT + n] : 0.f;
    __nv_bfloat16 h = __float2bfloat16(v);
    __nv_bfloat16 l = __float2bfloat16(v - __bfloat162float(h));
    oh[idx] = h;
    ol[idx] = l;
}

// ----------------------------- CSR build ----------------------------------

__global__ void hist_kernel(const int* __restrict__ dst, int E) {
    int i = blockIdx.x * blockDim.x + threadIdx.x;
    if (i < E) atomicAdd(&g_deg[dst[i]], 1);
}

__global__ void scan_phase1(int n) {
    __shared__ int sm[SCAN_CHUNK];
    int i = blockIdx.x * SCAN_CHUNK + threadIdx.x;
    int d = (i < n) ? g_deg[i] : 0;
    if (i < n) g_deg[i] = 0;
    sm[threadIdx.x] = d;
    __syncthreads();
#pragma unroll
    for (int o = 1; o < SCAN_CHUNK; o <<= 1) {
        int t = (threadIdx.x >= o) ? sm[threadIdx.x - o] : 0;
        __syncthreads();
        sm[threadIdx.x] += t;
        __syncthreads();
    }
    if (i < n) g_scan[i] = sm[threadIdx.x];
    if (threadIdx.x == SCAN_CHUNK - 1) g_bsum[blockIdx.x] = sm[SCAN_CHUNK - 1];
}

__global__ void scan_phase2(int nb) {
    int lane = threadIdx.x;
    int base = lane * 8;
    int v[8];
    int s = 0;
#pragma unroll
    for (int j = 0; j < 8; j++) {
        int x = (base + j < nb) ? g_bsum[base + j] : 0;
        v[j] = s;
        s += x;
    }
    int t = s;
#pragma unroll
    for (int o = 1; o < 32; o <<= 1) {
        int u = __shfl_up_sync(0xffffffffu, t, o);
        if (lane >= o) t += u;
    }
    int excl = t - s;
#pragma unroll
    for (int j = 0; j < 8; j++)
        if (base + j < nb) g_boff[base + j] = excl + v[j];
}

__global__ void scan_phase3(int n) {
    int i = blockIdx.x * blockDim.x + threadIdx.x;
    if (i < n) {
        int v = g_scan[i] + g_boff[i >> 9];
        g_off[i + 1] = v;
        if (i + 1 < n) g_cur[i + 1] = v;
    }
    if (i == 0) { g_off[0] = 0; g_cur[0] = 0; }
}

__global__ void scatter_kernel(const int* __restrict__ src, const int* __restrict__ dst, int E) {
    int i = blockIdx.x * blockDim.x + threadIdx.x;
    if (i >= E) return;
    int pos = atomicAdd(&g_cur[dst[i]], 1);
    g_srcs[pos] = src[i];
}

// ----------------------------- WMMA GEMM + fused logits --------------------
// Z[M,NOUT] = A[M,K] @ W[K,NOUT] via 3-term bf16 split:
//   A*W ~= Ah*Bh + Ah*Bl + Al*Bh   (fp32 accumulate)
// Block: 128 rows, 256 threads, 8 warps; warp = 16 rows x NPAD cols.
// K chunked by 64. As[r][0:64)=hi, [64:128)=lo; Bs rows [0:64)=Bh, [64:128)=Bl.

template<int K, int NOUT, int NPAD>
__global__ void __launch_bounds__(256)
gemm_wmma_kernel(const float* __restrict__ A,
                 const __nv_bfloat16* __restrict__ Bh,
                 const __nv_bfloat16* __restrict__ Bl,
                 const float* __restrict__ al, const float* __restrict__ ar,
                 float* __restrict__ Z, int M) {
    constexpr int CH  = K / 64;
    constexpr int NT  = NPAD / 16;
    constexpr int BLD = NPAD + 8;

    __shared__ __nv_bfloat16 As[128][136];
    __shared__ __nv_bfloat16 Bs[128][BLD];
    __shared__ float Cbuf[8][16][16];

    int tid  = threadIdx.x;
    int wid  = tid >> 5;
    int lane = tid & 31;
    int m0   = blockIdx.x * 128;

    wmma::fragment<wmma::accumulator, 16, 16, 16, float> c[NT];
#pragma unroll
    for (int nt = 0; nt < NT; nt++)
        wmma::fill_fragment(c[nt], 0.f);

    for (int ch = 0; ch < CH; ch++) {
        int k0 = ch * 64;
        // A chunk: 128 rows x 64 k; convert fp32 -> bf16 hi + residual lo.
#pragma unroll
        for (int t = 0; t < 8; t++) {
            int idx = tid + t * 256;
            int r   = idx >> 4;
            int c4  = (idx & 15) * 4;
            int row = m0 + r;
            float4 v = make_float4(0.f, 0.f, 0.f, 0.f);
            if (row < M) v = *(const float4*)&A[(size_t)row * K + k0 + c4];
            __nv_bfloat16 hx = __float2bfloat16(v.x);
            __nv_bfloat16 hy = __float2bfloat16(v.y);
            __nv_bfloat16 hz = __float2bfloat16(v.z);
            __nv_bfloat16 hw = __float2bfloat16(v.w);
            __nv_bfloat162 h01, h23, l01, l23;
            h01 = __nv_bfloat162(hx, hy);
            h23 = __nv_bfloat162(hz, hw);
            l01 = __floats2bfloat162_rn(v.x - __bfloat162float(hx),
                                        v.y - __bfloat162float(hy));
            l23 = __floats2bfloat162_rn(v.z - __bfloat162float(hz),
                                        v.w - __bfloat162float(hw));
            *(__nv_bfloat162*)&As[r][c4]          = h01;
            *(__nv_bfloat162*)&As[r][c4 + 2]      = h23;
            *(__nv_bfloat162*)&As[r][64 + c4]     = l01;
            *(__nv_bfloat162*)&As[r][64 + c4 + 2] = l23;
        }
        // B chunk: copy hi plane into rows [0,64), lo plane into rows [64,128).
        {
            constexpr int R8 = NPAD / 8;           // uint4 (8 bf16) per row
            for (int i = tid; i < 64 * R8 * 2; i += 256) {
                int plane = i / (64 * R8);
                int j     = i % (64 * R8);
                int k     = j / R8;
                int b8    = j % R8;
                const __nv_bfloat16* sp = plane ? Bl : Bh;
                uint4 v = *(const uint4*)&sp[(size_t)(k0 + k) * NPAD + b8 * 8];
                *(uint4*)&Bs[plane * 64 + k][b8 * 8] = v;
            }
        }
        __syncthreads();

#pragma unroll
        for (int t = 0; t < 3; t++) {
            const int aoff = (t == 2) ? 64 : 0;    // Ah, Ah, Al
            const int boff = (t == 1) ? 64 : 0;    // Bh, Bl, Bh
#pragma unroll
            for (int k16 = 0; k16 < 4; k16++) {
                wmma::fragment<wmma::matrix_a, 16, 16, 16, __nv_bfloat16, wmma::row_major> a;
                wmma::load_matrix_sync(a, &As[wid * 16][aoff + k16 * 16], 136);
#pragma unroll
                for (int nt = 0; nt < NT; nt++) {
                    wmma::fragment<wmma::matrix_b, 16, 16, 16, __nv_bfloat16, wmma::row_major> b;
                    wmma::load_matrix_sync(b, &Bs[boff + k16 * 16][nt * 16], BLD);
                    wmma::mma_sync(c[nt], a, b, c[nt]);
                }
            }
        }
        __syncthreads();
    }

    // Epilogue: stage each 16x16 tile in smem; coalesced Z writes + logits.
    float el = 0.f, er = 0.f;
    int myrow = m0 + wid * 16 + lane;              // valid for lane < 16
    float (*buf)[16] = Cbuf[wid];

#pragma unroll
    for (int nt = 0; nt < NT; nt++) {
        wmma::store_matrix_sync(&buf[0][0], c[nt], 16, wmma::mem_row_major);
        __syncwarp();
        if (lane < 16 && myrow < M) {
#pragma unroll
            for (int j = 0; j < 16; j++) {
                int col = nt * 16 + j;
                if (col < NOUT) {
                    float v = buf[lane][j];
                    el += v * al[col];
                    er += v * ar[col];
                }
            }
        }
#pragma unroll
        for (int rep = 0; rep < 2; rep++) {
            int idx = lane + rep * 32;
            int r   = idx >> 2;
            int c4  = idx & 3;
            int row = m0 + wid * 16 + r;
            int col = nt * 16 + c4 * 4;
            if (row < M && col < NOUT)
                *(float4*)&Z[(size_t)row * NOUT + col] = *(float4*)&buf[r][c4 * 4];
        }
        __syncwarp();
    }
    if (lane < 16 && myrow < M) { g_el[myrow] = el; g_er[myrow] = er; }
}

// --------------------- fused softmax + aggregation (round-4 best) ----------

__global__ void fused_agg1_kernel(const float* __restrict__ Z, const float* __restrict__ b,
                                  float* __restrict__ H, int n, float neg_slope) {
    int gw   = (blockIdx.x * blockDim.x + threadIdx.x) >> 5;
    int node = gw >> 1;
    int half = gw & 1;
    int lane = threadIdx.x & 31;
    if (node >= n) return;
    int start = g_off[node], end = g_off[node + 1];
    int deg   = end - start;
    float erd = g_er[node];
    int fo = half * 32 + lane;

    float accA = 0.f, accB = 0.f, sum = 0.f;

    if (deg <= 32) {
        bool v = lane < deg;
        int   s = v ? g_srcs[start + lane] : 0;
        float e = v ? (g_el[s] + erd) : -3.4e38f;
        e = (e > 0.f) ? e : neg_slope * e;
        float m = warp_max(e);
        float w = v ? expf(e - m) : 0.f;
        sum = w;
        int cnt8 = (deg + 7) & ~7;
        for (int j = 0; j < cnt8; j += 8) {
#pragma unroll
            for (int jj = 0; jj < 8; jj += 2) {
                int   s0 = __shfl_sync(0xffffffffu, s, j + jj);
                float w0 = __shfl_sync(0xffffffffu, w, j + jj);
                int   s1 = __shfl_sync(0xffffffffu, s, j + jj + 1);
                float w1 = __shfl_sync(0xffffffffu, w, j + jj + 1);
                accA += w0 * Z[(long long)s0 * 64 + fo];
                accB += w1 * Z[(long long)s1 * 64 + fo];
            }
        }
    } else {
        float m = -3.4e38f;
        for (int i = start + lane; i < end; i += 32) {
            float e = g_el[g_srcs[i]] + erd;
            e = (e > 0.f) ? e : neg_slope * e;
            m = fmaxf(m, e);
        }
        m = warp_max(m);
        for (int c = start; c < end; c += 32) {
            int idx = c + lane;
            bool v = idx < end;
            int   s = v ? g_srcs[idx] : 0;
            float e = v ? (g_el[s] + erd) : -3.4e38f;
            e = (e > 0.f) ? e : neg_slope * e;
            float w = v ? expf(e - m) : 0.f;
            sum += w;
            int cnt  = min(32, end - c);
            int cnt8 = (cnt + 7) & ~7;
            for (int j = 0; j < cnt8; j += 8) {
#pragma unroll
                for (int jj = 0; jj < 8; jj += 2) {
                    int   s0 = __shfl_sync(0xffffffffu, s, j + jj);
                    float w0 = __shfl_sync(0xffffffffu, w, j + jj);
                    int   s1 = __shfl_sync(0xffffffffu, s, j + jj + 1);
                    float w1 = __shfl_sync(0xffffffffu, w, j + jj + 1);
                    accA += w0 * Z[(long long)s0 * 64 + fo];
                    accB += w1 * Z[(long long)s1 * 64 + fo];
                }
            }
        }
    }

    sum = warp_sum(sum);
    float sinv = (deg > 0) ? 1.f / sum : 0.f;
    float v0 = (accA + accB) * sinv + b[fo];
    H[(long long)node * 64 + fo] = (v0 > 0.f) ? v0 : 0.f;
}

__global__ void fused_agg2_kernel(const float* __restrict__ Z, const float* __restrict__ b,
                                  float* __restrict__ out, int n, float neg_slope) {
    int gw   = (blockIdx.x * blockDim.x + threadIdx.x) >> 5;
    int node = gw;
    int lane = threadIdx.x & 31;
    if (node >= n) return;
    int start = g_off[node], end = g_off[node + 1];
    int deg   = end - start;
    float erd = g_er[node];
    bool h1 = lane < 8;

    float accA = 0.f, accB = 0.f, acc1 = 0.f, sum = 0.f;

    if (deg <= 32) {
        bool v = lane < deg;
        int   s = v ? g_srcs[start + lane] : 0;
        float e = v ? (g_el[s] + erd) : -3.4e38f;
        e = (e > 0.f) ? e : neg_slope * e;
        float m = warp_max(e);
        float w = v ? expf(e - m) : 0.f;
        sum = w;
        int cnt8 = (deg + 7) & ~7;
        for (int j = 0; j < cnt8; j += 8) {
#pragma unroll
            for (int jj = 0; jj < 8; jj += 2) {
                int   s0 = __shfl_sync(0xffffffffu, s, j + jj);
                float w0 = __shfl_sync(0xffffffffu, w, j + jj);
                int   s1 = __shfl_sync(0xffffffffu, s, j + jj + 1);
                float w1 = __shfl_sync(0xffffffffu, w, j + jj + 1);
                const float* z0 = Z + (long long)s0 * 40;
                const float* z1 = Z + (long long)s1 * 40;
                accA += w0 * z0[lane];
                accB += w1 * z1[lane];
                if (h1) acc1 += w0 * z0[lane + 32] + w1 * z1[lane + 32];
            }
        }
    } else {
        float m = -3.4e38f;
        for (int i = start + lane; i < end; i += 32) {
            float e = g_el[g_srcs[i]] + erd;
            e = (e > 0.f) ? e : neg_slope * e;
            m = fmaxf(m, e);
        }
        m = warp_max(m);
        for (int c = start; c < end; c += 32) {
            int idx = c + lane;
            bool v = idx < end;
            int   s = v ? g_srcs[idx] : 0;
            float e = v ? (g_el[s] + erd) : -3.4e38f;
            e = (e > 0.f) ? e : neg_slope * e;
            float w = v ? expf(e - m) : 0.f;
            sum += w;
            int cnt  = min(32, end - c);
            int cnt8 = (cnt + 7) & ~7;
            for (int j = 0; j < cnt8; j += 8) {
#pragma unroll
                for (int jj = 0; jj < 8; jj += 2) {
                    int   s0 = __shfl_sync(0xffffffffu, s, j + jj);
                    float w0 = __shfl_sync(0xffffffffu, w, j + jj);
                    int   s1 = __shfl_sync(0xffffffffu, s, j + jj + 1);
                    float w1 = __shfl_sync(0xffffffffu, w, j + jj + 1);
                    const float* z0 = Z + (long long)s0 * 40;
                    const float* z1 = Z + (long long)s1 * 40;
                    accA += w0 * z0[lane];
                    accB += w1 * z1[lane];
                    if (h1) acc1 += w0 * z0[lane + 32] + w1 * z1[lane + 32];
                }
            }
        }
    }

    sum = warp_sum(sum);
    float sinv = (deg > 0) ? 1.f / sum : 0.f;
    float v0 = (accA + accB) * sinv + b[lane];
    float v1 = h1 ? (acc1 * sinv + b[lane + 32]) : -3.4e38f;

    float mx = warp_max(fmaxf(v0, v1));
    float se = warp_sum(expf(v0 - mx) + (h1 ? expf(v1 - mx) : 0.f));
    float lse = mx + logf(se);

    long long base = (long long)node * 40;
    out[base + lane] = v0 - lse;
    if (h1) out[base + lane + 32] = v1 - lse;
}

// ----------------------------- host launch ---------------------------------

extern "C" void kernel_launch(void* const* d_in, const int* in_sizes, int n_in,
                              void* d_out, int out_size) {
    const float* feat = (const float*)d_in[0];
    const int*   src  = (const int*)  d_in[1];
    const int*   dst  = (const int*)  d_in[2];
    const float* W1   = (const float*)d_in[3];
    const float* b1   = (const float*)d_in[4];
    const float* al1  = (const float*)d_in[5];
    const float* ar1  = (const float*)d_in[6];
    const float* W2   = (const float*)d_in[7];
    const float* b2   = (const float*)d_in[8];
    const float* al2  = (const float*)d_in[9];
    const float* ar2  = (const float*)d_in[10];
    float* out = (float*)d_out;

    const int IN = 256;
    int n = in_sizes[0] / IN;   // 100000
    int E = in_sizes[1];        // 1600000

    float* zp; cudaGetSymbolAddress((void**)&zp, g_z);
    float* hp; cudaGetSymbolAddress((void**)&hp, g_h);
    __nv_bfloat16 *bt1h, *bt1l, *bt2h, *bt2l;
    cudaGetSymbolAddress((void**)&bt1h, g_bt1h);
    cudaGetSymbolAddress((void**)&bt1l, g_bt1l);
    cudaGetSymbolAddress((void**)&bt2h, g_bt2h);
    cudaGetSymbolAddress((void**)&bt2l, g_bt2l);

    const float NEG_SLOPE = 0.2f;
    int mb128 = (n + 127) / 128;
    int nb_scan = (n + SCAN_CHUNK - 1) / SCAN_CHUNK;

    // gemm1 at stream launch index 3 (profiler's capture slot).
    wconv_kernel<<<(256 * 64 + 255) / 256, 256>>>(W1, 256, 64, 64, bt1h, bt1l);      // 0
    hist_kernel<<<(E + 255) / 256, 256>>>(dst, E);                                   // 1
    scan_phase1<<<nb_scan, SCAN_CHUNK>>>(n);                                         // 2
    gemm_wmma_kernel<256, 64, 64><<<mb128, 256>>>(feat, bt1h, bt1l, al1, ar1, zp, n);// 3 <- profiled
    wconv_kernel<<<(64 * 48 + 255) / 256, 256>>>(W2, 64, 40, 48, bt2h, bt2l);        // 4
    scan_phase2<<<1, 32>>>(nb_scan);                                                 // 5
    scan_phase3<<<(n + 255) / 256, 256>>>(n);                                        // 6
    scatter_kernel<<<(E + 255) / 256, 256>>>(src, dst, E);                           // 7

    fused_agg1_kernel<<<(2 * n * 32 + 255) / 256, 256>>>(zp, b1, hp, n, NEG_SLOPE);  // 8
    gemm_wmma_kernel<64, 40, 48><<<mb128, 256>>>(hp, bt2h, bt2l, al2, ar2, zp, n);   // 9
    fused_agg2_kernel<<<(n * 32 + 255) / 256, 256>>>(zp, b2, out, n, NEG_SLOPE);     // 10
}

// round 9
// speedup vs baseline: 1.2113x; 1.2113x over previous
#include <cuda_runtime.h>
#include <cuda_bf16.h>
#include <mma.h>
#include <math.h>
#include <stdint.h>

using namespace nvcuda;

// ---------------------------------------------------------------------------
// DenseGAT: 2-layer GAT, N=100000 nodes, E=1600000 edges, 256 -> 64 -> 40
// bf16-split WMMA GEMM (2 CTAs/SM) + fused logits; CSR; full-row gather agg.
// ---------------------------------------------------------------------------

#define MAX_NODES 100000
#define MAX_EDGES 1600000
#define SCAN_CHUNK 512
#define MAX_BLOCKS_SCAN 256

__device__ float g_z   [MAX_NODES * 64];
__device__ float g_h   [MAX_NODES * 64];
__device__ float g_el  [MAX_NODES];
__device__ float g_er  [MAX_NODES];
__device__ int   g_deg [MAX_NODES];
__device__ int   g_scan[MAX_NODES];
__device__ int   g_off [MAX_NODES + 1];
__device__ int   g_cur [MAX_NODES];
__device__ int   g_srcs[MAX_EDGES];
__device__ int   g_bsum[MAX_BLOCKS_SCAN];
__device__ int   g_boff[MAX_BLOCKS_SCAN];

// bf16 hi/lo W planes, row-major padded: layer1 [256][64], layer2 [64][48]
__device__ __align__(16) __nv_bfloat16 g_bt1h[256 * 64];
__device__ __align__(16) __nv_bfloat16 g_bt1l[256 * 64];
__device__ __align__(16) __nv_bfloat16 g_bt2h[64 * 48];
__device__ __align__(16) __nv_bfloat16 g_bt2l[64 * 48];

__device__ __forceinline__ float warp_max(float v) {
#pragma unroll
    for (int o = 16; o > 0; o >>= 1)
        v = fmaxf(v, __shfl_xor_sync(0xffffffffu, v, o));
    return v;
}
__device__ __forceinline__ float warp_sum(float v) {
#pragma unroll
    for (int o = 16; o > 0; o >>= 1)
        v += __shfl_xor_sync(0xffffffffu, v, o);
    return v;
}

// ----------------------------- W convert ----------------------------------

__global__ void wconv_kernel(const float* __restrict__ W, int K, int NOUT, int NPAD,
                             __nv_bfloat16* __restrict__ oh, __nv_bfloat16* __restrict__ ol) {
    int idx = blockIdx.x * blockDim.x + threadIdx.x;
    if (idx >= K * NPAD) return;
    int k = idx / NPAD;
    int n = idx % NPAD;
    float v = (n < NOUT) ? W[k * NOUT + n] : 0.f;
    __nv_bfloat16 h = __float2bfloat16(v);
    __nv_bfloat16 l = __float2bfloat16(v - __bfloat162float(h));
    oh[idx] = h;
    ol[idx] = l;
}

// ----------------------------- CSR build ----------------------------------

__global__ void hist_kernel(const int* __restrict__ dst, int E) {
    int i = blockIdx.x * blockDim.x + threadIdx.x;
    if (i < E) atomicAdd(&g_deg[dst[i]], 1);
}

__global__ void scan_phase1(int n) {
    __shared__ int sm[SCAN_CHUNK];
    int i = blockIdx.x * SCAN_CHUNK + threadIdx.x;
    int d = (i < n) ? g_deg[i] : 0;
    if (i < n) g_deg[i] = 0;
    sm[threadIdx.x] = d;
    __syncthreads();
#pragma unroll
    for (int o = 1; o < SCAN_CHUNK; o <<= 1) {
        int t = (threadIdx.x >= o) ? sm[threadIdx.x - o] : 0;
        __syncthreads();
        sm[threadIdx.x] += t;
        __syncthreads();
    }
    if (i < n) g_scan[i] = sm[threadIdx.x];
    if (threadIdx.x == SCAN_CHUNK - 1) g_bsum[blockIdx.x] = sm[SCAN_CHUNK - 1];
}

__global__ void scan_phase2(int nb) {
    int lane = threadIdx.x;
    int base = lane * 8;
    int v[8];
    int s = 0;
#pragma unroll
    for (int j = 0; j < 8; j++) {
        int x = (base + j < nb) ? g_bsum[base + j] : 0;
        v[j] = s;
        s += x;
    }
    int t = s;
#pragma unroll
    for (int o = 1; o < 32; o <<= 1) {
        int u = __shfl_up_sync(0xffffffffu, t, o);
        if (lane >= o) t += u;
    }
    int excl = t - s;
#pragma unroll
    for (int j = 0; j < 8; j++)
        if (base + j < nb) g_boff[base + j] = excl + v[j];
}

__global__ void scan_phase3(int n) {
    int i = blockIdx.x * blockDim.x + threadIdx.x;
    if (i < n) {
        int v = g_scan[i] + g_boff[i >> 9];
        g_off[i + 1] = v;
        if (i + 1 < n) g_cur[i + 1] = v;
    }
    if (i == 0) { g_off[0] = 0; g_cur[0] = 0; }
}

__global__ void scatter_kernel(const int* __restrict__ src, const int* __restrict__ dst, int E) {
    int i = blockIdx.x * blockDim.x + threadIdx.x;
    if (i >= E) return;
    int pos = atomicAdd(&g_cur[dst[i]], 1);
    g_srcs[pos] = src[i];
}

// ----------------------------- WMMA GEMM + fused logits --------------------
// 3-term bf16 split: A*W ~= Ah*Bh + Ah*Bl + Al*Bh (fp32 accum).
// 256 threads / 8 warps / 128 rows; K-chunk 32 (As: 32 hi + 32 lo cols).
// smem ~28KB, __launch_bounds__(256,2) -> 2 CTAs/SM. Cbuf unions onto As.

template<int K, int NOUT, int NPAD>
__global__ void __launch_bounds__(256, 2)
gemm_wmma_kernel(const float* __restrict__ A,
                 const __nv_bfloat16* __restrict__ Bh,
                 const __nv_bfloat16* __restrict__ Bl,
                 const float* __restrict__ al, const float* __restrict__ ar,
                 float* __restrict__ Z, int M) {
    constexpr int CH  = K / 32;
    constexpr int NT  = NPAD / 16;
    constexpr int ALD = 72;            // 32 hi + 32 lo + 8 pad
    constexpr int BLD = NPAD + 8;
    constexpr int ABYTES = 128 * ALD * 2;

    __shared__ __align__(16) unsigned char sraw[ABYTES + 64 * BLD * 2];
    __nv_bfloat16 (*As)[ALD] = (__nv_bfloat16(*)[ALD])sraw;
    __nv_bfloat16 (*Bs)[BLD] = (__nv_bfloat16(*)[BLD])(sraw + ABYTES);

    int tid  = threadIdx.x;
    int wid  = tid >> 5;
    int lane = tid & 31;
    int m0   = blockIdx.x * 128;

    wmma::fragment<wmma::accumulator, 16, 16, 16, float> c[NT];
#pragma unroll
    for (int nt = 0; nt < NT; nt++)
        wmma::fill_fragment(c[nt], 0.f);

    for (int ch = 0; ch < CH; ch++) {
        int k0 = ch * 32;
        // A chunk: 128 rows x 32 k -> bf16 hi + residual lo (4 float4/thread).
#pragma unroll
        for (int t = 0; t < 4; t++) {
            int idx = tid + t * 256;
            int r   = idx >> 3;
            int c4  = (idx & 7) * 4;
            int row = m0 + r;
            float4 v = make_float4(0.f, 0.f, 0.f, 0.f);
            if (row < M) v = *(const float4*)&A[(size_t)row * K + k0 + c4];
            __nv_bfloat16 hx = __float2bfloat16(v.x);
            __nv_bfloat16 hy = __float2bfloat16(v.y);
            __nv_bfloat16 hz = __float2bfloat16(v.z);
            __nv_bfloat16 hw = __float2bfloat16(v.w);
            *(__nv_bfloat162*)&As[r][c4]          = __nv_bfloat162(hx, hy);
            *(__nv_bfloat162*)&As[r][c4 + 2]      = __nv_bfloat162(hz, hw);
            *(__nv_bfloat162*)&As[r][32 + c4]     =
                __floats2bfloat162_rn(v.x - __bfloat162float(hx), v.y - __bfloat162float(hy));
            *(__nv_bfloat162*)&As[r][32 + c4 + 2] =
                __floats2bfloat162_rn(v.z - __bfloat162float(hz), v.w - __bfloat162float(hw));
        }
        // B chunk: hi rows [0,32), lo rows [32,64).
        {
            constexpr int R8 = NPAD / 8;
            for (int i = tid; i < 32 * R8 * 2; i += 256) {
                int plane = i / (32 * R8);
                int j     = i % (32 * R8);
                int k     = j / R8;
                int b8    = j % R8;
                const __nv_bfloat16* sp = plane ? Bl : Bh;
                uint4 v = *(const uint4*)&sp[(size_t)(k0 + k) * NPAD + b8 * 8];
                *(uint4*)&Bs[plane * 32 + k][b8 * 8] = v;
            }
        }
        __syncthreads();

#pragma unroll
        for (int k16 = 0; k16 < 2; k16++) {
            wmma::fragment<wmma::matrix_a, 16, 16, 16, __nv_bfloat16, wmma::row_major> ah, alo;
            wmma::load_matrix_sync(ah,  &As[wid * 16][k16 * 16],      ALD);
            wmma::load_matrix_sync(alo, &As[wid * 16][32 + k16 * 16], ALD);
#pragma unroll
            for (int nt = 0; nt < NT; nt++) {
                wmma::fragment<wmma::matrix_b, 16, 16, 16, __nv_bfloat16, wmma::row_major> bh, bl;
                wmma::load_matrix_sync(bh, &Bs[k16 * 16][nt * 16],      BLD);
                wmma::load_matrix_sync(bl, &Bs[32 + k16 * 16][nt * 16], BLD);
                wmma::mma_sync(c[nt], ah,  bh, c[nt]);
                wmma::mma_sync(c[nt], ah,  bl, c[nt]);
                wmma::mma_sync(c[nt], alo, bh, c[nt]);
            }
        }
        __syncthreads();
    }

    // Epilogue: Cbuf reuses the As region (mainloop done for whole CTA).
    float (*Cbuf)[16][16] = (float(*)[16][16])sraw;
    float (*buf)[16] = Cbuf[wid];
    float el = 0.f, er = 0.f;
    int myrow = m0 + wid * 16 + lane;              // valid for lane < 16

#pragma unroll
    for (int nt = 0; nt < NT; nt++) {
        wmma::store_matrix_sync(&buf[0][0], c[nt], 16, wmma::mem_row_major);
        __syncwarp();
        if (lane < 16 && myrow < M) {
#pragma unroll
            for (int j = 0; j < 16; j++) {
                int col = nt * 16 + j;
                if (col < NOUT) {
                    float v = buf[lane][j];
                    el += v * al[col];
                    er += v * ar[col];
                }
            }
        }
#pragma unroll
        for (int rep = 0; rep < 2; rep++) {
            int idx = lane + rep * 32;
            int r   = idx >> 2;
            int c4  = idx & 3;
            int row = m0 + wid * 16 + r;
            int col = nt * 16 + c4 * 4;
            if (row < M && col < NOUT)
                *(float4*)&Z[(size_t)row * NOUT + col] = *(float4*)&buf[r][c4 * 4];
        }
        __syncwarp();
    }
    if (lane < 16 && myrow < M) { g_el[myrow] = el; g_er[myrow] = er; }
}

// --------------------- fused softmax + aggregation ------------------------
// Layer 1: ONE warp per node, full 64-feature row. Per broadcast edge: two
// independent 128B-line LDGs; 4-edge unroll => 8 outstanding loads per warp.

__global__ void fused_agg1_kernel(const float* __restrict__ Z, const float* __restrict__ b,
                                  float* __restrict__ H, int n, float neg_slope) {
    int node = (blockIdx.x * blockDim.x + threadIdx.x) >> 5;
    int lane = threadIdx.x & 31;
    if (node >= n) return;
    int start = g_off[node], end = g_off[node + 1];
    int deg   = end - start;
    float erd = g_er[node];

    float aL0 = 0.f, aL1 = 0.f, aH0 = 0.f, aH1 = 0.f, sum = 0.f;

    if (deg <= 32) {
        bool v = lane < deg;
        int   s = v ? g_srcs[start + lane] : 0;
        float e = v ? (g_el[s] + erd) : -3.4e38f;
        e = (e > 0.f) ? e : neg_slope * e;
        float m = warp_max(e);
        float w = v ? expf(e - m) : 0.f;
        sum = w;
        int cnt4 = (deg + 3) & ~3;
        for (int j = 0; j < cnt4; j += 4) {
            int   s0 = __shfl_sync(0xffffffffu, s, j);
            float w0 = __shfl_sync(0xffffffffu, w, j);
            int   s1 = __shfl_sync(0xffffffffu, s, j + 1);
            float w1 = __shfl_sync(0xffffffffu, w, j + 1);
            int   s2 = __shfl_sync(0xffffffffu, s, j + 2);
            float w2 = __shfl_sync(0xffffffffu, w, j + 2);
            int   s3 = __shfl_sync(0xffffffffu, s, j + 3);
            float w3 = __shfl_sync(0xffffffffu, w, j + 3);
            const float* z0 = Z + (long long)s0 * 64;
            const float* z1 = Z + (long long)s1 * 64;
            const float* z2 = Z + (long long)s2 * 64;
            const float* z3 = Z + (long long)s3 * 64;
            aL0 += w0 * z0[lane];  aH0 += w0 * z0[lane + 32];
            aL1 += w1 * z1[lane];  aH1 += w1 * z1[lane + 32];
            aL0 += w2 * z2[lane];  aH0 += w2 * z2[lane + 32];
            aL1 += w3 * z3[lane];  aH1 += w3 * z3[lane + 32];
        }
    } else {
        float m = -3.4e38f;
        for (int i = start + lane; i < end; i += 32) {
            float e = g_el[g_srcs[i]] + erd;
            e = (e > 0.f) ? e : neg_slope * e;
            m = fmaxf(m, e);
        }
        m = warp_max(m);
        for (int c = start; c < end; c += 32) {
            int idx = c + lane;
            bool v = idx < end;
            int   s = v ? g_srcs[idx] : 0;
            float e = v ? (g_el[s] + erd) : -3.4e38f;
            e = (e > 0.f) ? e : neg_slope * e;
            float w = v ? expf(e - m) : 0.f;
            sum += w;
            int cnt  = min(32, end - c);
            int cnt4 = (cnt + 3) & ~3;
            for (int j = 0; j < cnt4; j += 4) {
                int   s0 = __shfl_sync(0xffffffffu, s, j);
                float w0 = __shfl_sync(0xffffffffu, w, j);
                int   s1 = __shfl_sync(0xffffffffu, s, j + 1);
                float w1 = __shfl_sync(0xffffffffu, w, j + 1);
                int   s2 = __shfl_sync(0xffffffffu, s, j + 2);
                float w2 = __shfl_sync(0xffffffffu, w, j + 2);
                int   s3 = __shfl_sync(0xffffffffu, s, j + 3);
                float w3 = __shfl_sync(0xffffffffu, w, j + 3);
                const float* z0 = Z + (long long)s0 * 64;
                const float* z1 = Z + (long long)s1 * 64;
                const float* z2 = Z + (long long)s2 * 64;
                const float* z3 = Z + (long long)s3 * 64;
                aL0 += w0 * z0[lane];  aH0 += w0 * z0[lane + 32];
                aL1 += w1 * z1[lane];  aH1 += w1 * z1[lane + 32];
                aL0 += w2 * z2[lane];  aH0 += w2 * z2[lane + 32];
                aL1 += w3 * z3[lane];  aH1 += w3 * z3[lane + 32];
            }
        }
    }

    sum = warp_sum(sum);
    float sinv = (deg > 0) ? 1.f / sum : 0.f;
    float vL = (aL0 + aL1) * sinv + b[lane];
    float vH = (aH0 + aH1) * sinv + b[lane + 32];
    H[(long long)node * 64 + lane]      = (vL > 0.f) ? vL : 0.f;
    H[(long long)node * 64 + lane + 32] = (vH > 0.f) ? vH : 0.f;
}

// Layer 2: 1 warp per node, F = 40, fused bias + log_softmax (round-4 form).
__global__ void fused_agg2_kernel(const float* __restrict__ Z, const float* __restrict__ b,
                                  float* __restrict__ out, int n, float neg_slope) {
    int gw   = (blockIdx.x * blockDim.x + threadIdx.x) >> 5;
    int node = gw;
    int lane = threadIdx.x & 31;
    if (node >= n) return;
    int start = g_off[node], end = g_off[node + 1];
    int deg   = end - start;
    float erd = g_er[node];
    bool h1 = lane < 8;

    float accA = 0.f, accB = 0.f, acc1 = 0.f, sum = 0.f;

    if (deg <= 32) {
        bool v = lane < deg;
        int   s = v ? g_srcs[start + lane] : 0;
        float e = v ? (g_el[s] + erd) : -3.4e38f;
        e = (e > 0.f) ? e : neg_slope * e;
        float m = warp_max(e);
        float w = v ? expf(e - m) : 0.f;
        sum = w;
        int cnt8 = (deg + 7) & ~7;
        for (int j = 0; j < cnt8; j += 8) {
#pragma unroll
            for (int jj = 0; jj < 8; jj += 2) {
                int   s0 = __shfl_sync(0xffffffffu, s, j + jj);
                float w0 = __shfl_sync(0xffffffffu, w, j + jj);
                int   s1 = __shfl_sync(0xffffffffu, s, j + jj + 1);
                float w1 = __shfl_sync(0xffffffffu, w, j + jj + 1);
                const float* z0 = Z + (long long)s0 * 40;
                const float* z1 = Z + (long long)s1 * 40;
                accA += w0 * z0[lane];
                accB += w1 * z1[lane];
                if (h1) acc1 += w0 * z0[lane + 32] + w1 * z1[lane + 32];
            }
        }
    } else {
        float m = -3.4e38f;
        for (int i = start + lane; i < end; i += 32) {
            float e = g_el[g_srcs[i]] + erd;
            e = (e > 0.f) ? e : neg_slope * e;
            m = fmaxf(m, e);
        }
        m = warp_max(m);
        for (int c = start; c < end; c += 32) {
            int idx = c + lane;
            bool v = idx < end;
            int   s = v ? g_srcs[idx] : 0;
            float e = v ? (g_el[s] + erd) : -3.4e38f;
            e = (e > 0.f) ? e : neg_slope * e;
            float w = v ? expf(e - m) : 0.f;
            sum += w;
            int cnt  = min(32, end - c);
            int cnt8 = (cnt + 7) & ~7;
            for (int j = 0; j < cnt8; j += 8) {
#pragma unroll
                for (int jj = 0; jj < 8; jj += 2) {
                    int   s0 = __shfl_sync(0xffffffffu, s, j + jj);
                    float w0 = __shfl_sync(0xffffffffu, w, j + jj);
                    int   s1 = __shfl_sync(0xffffffffu, s, j + jj + 1);
                    float w1 = __shfl_sync(0xffffffffu, w, j + jj + 1);
                    const float* z0 = Z + (long long)s0 * 40;
                    const float* z1 = Z + (long long)s1 * 40;
                    accA += w0 * z0[lane];
                    accB += w1 * z1[lane];
                    if (h1) acc1 += w0 * z0[lane + 32] + w1 * z1[lane + 32];
                }
            }
        }
    }

    sum = warp_sum(sum);
    float sinv = (deg > 0) ? 1.f / sum : 0.f;
    float v0 = (accA + accB) * sinv + b[lane];
    float v1 = h1 ? (acc1 * sinv + b[lane + 32]) : -3.4e38f;

    float mx = warp_max(fmaxf(v0, v1));
    float se = warp_sum(expf(v0 - mx) + (h1 ? expf(v1 - mx) : 0.f));
    float lse = mx + logf(se);

    long long base = (long long)node * 40;
    out[base + lane] = v0 - lse;
    if (h1) out[base + lane + 32] = v1 - lse;
}

// ----------------------------- host launch ---------------------------------

extern "C" void kernel_launch(void* const* d_in, const int* in_sizes, int n_in,
                              void* d_out, int out_size) {
    const float* feat = (const float*)d_in[0];
    const int*   src  = (const int*)  d_in[1];
    const int*   dst  = (const int*)  d_in[2];
    const float* W1   = (const float*)d_in[3];
    const float* b1   = (const float*)d_in[4];
    const float* al1  = (const float*)d_in[5];
    const float* ar1  = (const float*)d_in[6];
    const float* W2   = (const float*)d_in[7];
    const float* b2   = (const float*)d_in[8];
    const float* al2  = (const float*)d_in[9];
    const float* ar2  = (const float*)d_in[10];
    float* out = (float*)d_out;

    const int IN = 256;
    int n = in_sizes[0] / IN;   // 100000
    int E = in_sizes[1];        // 1600000

    float* zp; cudaGetSymbolAddress((void**)&zp, g_z);
    float* hp; cudaGetSymbolAddress((void**)&hp, g_h);
    __nv_bfloat16 *bt1h, *bt1l, *bt2h, *bt2l;
    cudaGetSymbolAddress((void**)&bt1h, g_bt1h);
    cudaGetSymbolAddress((void**)&bt1l, g_bt1l);
    cudaGetSymbolAddress((void**)&bt2h, g_bt2h);
    cudaGetSymbolAddress((void**)&bt2l, g_bt2l);

    const float NEG_SLOPE = 0.2f;
    int mb128 = (n + 127) / 128;
    int nb_scan = (n + SCAN_CHUNK - 1) / SCAN_CHUNK;

    // gemm1 at stream launch index 3 (profiler's capture slot).
    wconv_kernel<<<(256 * 64 + 255) / 256, 256>>>(W1, 256, 64, 64, bt1h, bt1l);      // 0
    hist_kernel<<<(E + 255) / 256, 256>>>(dst, E);                                   // 1
    scan_phase1<<<nb_scan, SCAN_CHUNK>>>(n);                                         // 2
    gemm_wmma_kernel<256, 64, 64><<<mb128, 256>>>(feat, bt1h, bt1l, al1, ar1, zp, n);// 3 <- profiled
    wconv_kernel<<<(64 * 48 + 255) / 256, 256>>>(W2, 64, 40, 48, bt2h, bt2l);        // 4
    scan_phase2<<<1, 32>>>(nb_scan);                                                 // 5
    scan_phase3<<<(n + 255) / 256, 256>>>(n);                                        // 6
    scatter_kernel<<<(E + 255) / 256, 256>>>(src, dst, E);                           // 7

    fused_agg1_kernel<<<(n * 32 + 255) / 256, 256>>>(zp, b1, hp, n, NEG_SLOPE);      // 8
    gemm_wmma_kernel<64, 40, 48><<<mb128, 256>>>(hp, bt2h, bt2l, al2, ar2, zp, n);   // 9
    fused_agg2_kernel<<<(n * 32 + 255) / 256, 256>>>(zp, b2, out, n, NEG_SLOPE);     // 10
}

// round 10
// speedup vs baseline: 1.2496x; 1.0316x over previous
#include <cuda_runtime.h>
#include <cuda_bf16.h>
#include <mma.h>
#include <math.h>
#include <stdint.h>

using namespace nvcuda;

// ---------------------------------------------------------------------------
// DenseGAT: 2-layer GAT, N=100000 nodes, E=1600000 edges, 256 -> 64 -> 40
// bf16-split WMMA GEMM (K-chunk 64, 2 CTAs/SM, A-prefetch) + fused logits;
// CSR-by-dst; round-9 gather aggregation (measured best).
// ---------------------------------------------------------------------------

#define MAX_NODES 100000
#define MAX_EDGES 1600000
#define SCAN_CHUNK 512
#define MAX_BLOCKS_SCAN 256

__device__ float g_z   [MAX_NODES * 64];
__device__ float g_h   [MAX_NODES * 64];
__device__ float g_el  [MAX_NODES];
__device__ float g_er  [MAX_NODES];
__device__ int   g_deg [MAX_NODES];
__device__ int   g_scan[MAX_NODES];
__device__ int   g_off [MAX_NODES + 1];
__device__ int   g_cur [MAX_NODES];
__device__ int   g_srcs[MAX_EDGES];
__device__ int   g_bsum[MAX_BLOCKS_SCAN];
__device__ int   g_boff[MAX_BLOCKS_SCAN];

// bf16 hi/lo W planes, row-major padded: layer1 [256][64], layer2 [64][48]
__device__ __align__(16) __nv_bfloat16 g_bt1h[256 * 64];
__device__ __align__(16) __nv_bfloat16 g_bt1l[256 * 64];
__device__ __align__(16) __nv_bfloat16 g_bt2h[64 * 48];
__device__ __align__(16) __nv_bfloat16 g_bt2l[64 * 48];

__device__ __forceinline__ float warp_max(float v) {
#pragma unroll
    for (int o = 16; o > 0; o >>= 1)
        v = fmaxf(v, __shfl_xor_sync(0xffffffffu, v, o));
    return v;
}
__device__ __forceinline__ float warp_sum(float v) {
#pragma unroll
    for (int o = 16; o > 0; o >>= 1)
        v += __shfl_xor_sync(0xffffffffu, v, o);
    return v;
}

// ----------------------------- W convert ----------------------------------

__global__ void wconv_kernel(const float* __restrict__ W, int K, int NOUT, int NPAD,
                             __nv_bfloat16* __restrict__ oh, __nv_bfloat16* __restrict__ ol) {
    int idx = blockIdx.x * blockDim.x + threadIdx.x;
    if (idx >= K * NPAD) return;
    int k = idx / NPAD;
    int n = idx % NPAD;
    float v = (n < NOUT) ? W[k * NOUT + n] : 0.f;
    __nv_bfloat16 h = __float2bfloat16(v);
    __nv_bfloat16 l = __float2bfloat16(v - __bfloat162float(h));
    oh[idx] = h;
    ol[idx] = l;
}

// ----------------------------- CSR build ----------------------------------

__global__ void hist_kernel(const int* __restrict__ dst, int E) {
    int i = blockIdx.x * blockDim.x + threadIdx.x;
    if (i < E) atomicAdd(&g_deg[dst[i]], 1);
}

__global__ void scan_phase1(int n) {
    __shared__ int sm[SCAN_CHUNK];
    int i = blockIdx.x * SCAN_CHUNK + threadIdx.x;
    int d = (i < n) ? g_deg[i] : 0;
    if (i < n) g_deg[i] = 0;
    sm[threadIdx.x] = d;
    __syncthreads();
#pragma unroll
    for (int o = 1; o < SCAN_CHUNK; o <<= 1) {
        int t = (threadIdx.x >= o) ? sm[threadIdx.x - o] : 0;
        __syncthreads();
        sm[threadIdx.x] += t;
        __syncthreads();
    }
    if (i < n) g_scan[i] = sm[threadIdx.x];
    if (threadIdx.x == SCAN_CHUNK - 1) g_bsum[blockIdx.x] = sm[SCAN_CHUNK - 1];
}

__global__ void scan_phase2(int nb) {
    int lane = threadIdx.x;
    int base = lane * 8;
    int v[8];
    int s = 0;
#pragma unroll
    for (int j = 0; j < 8; j++) {
        int x = (base + j < nb) ? g_bsum[base + j] : 0;
        v[j] = s;
        s += x;
    }
    int t = s;
#pragma unroll
    for (int o = 1; o < 32; o <<= 1) {
        int u = __shfl_up_sync(0xffffffffu, t, o);
        if (lane >= o) t += u;
    }
    int excl = t - s;
#pragma unroll
    for (int j = 0; j < 8; j++)
        if (base + j < nb) g_boff[base + j] = excl + v[j];
}

__global__ void scan_phase3(int n) {
    int i = blockIdx.x * blockDim.x + threadIdx.x;
    if (i < n) {
        int v = g_scan[i] + g_boff[i >> 9];
        g_off[i + 1] = v;
        if (i + 1 < n) g_cur[i + 1] = v;
    }
    if (i == 0) { g_off[0] = 0; g_cur[0] = 0; }
}

__global__ void scatter_kernel(const int* __restrict__ src, const int* __restrict__ dst, int E) {
    int i = blockIdx.x * blockDim.x + threadIdx.x;
    if (i >= E) return;
    int pos = atomicAdd(&g_cur[dst[i]], 1);
    g_srcs[pos] = src[i];
}

// ----------------------------- WMMA GEMM + fused logits --------------------
// 3-term bf16 split: A*W ~= Ah*Bh + Ah*Bl + Al*Bh (fp32 accum).
// 256 threads / 8 warps / 128 rows; K-chunk 64 (As: 64 hi + 64 lo cols).
// smem ~53KB, __launch_bounds__(256,2) -> 2 CTAs/SM. Next-chunk A prefetched
// into registers under the MMA block. Cbuf unions onto As for the epilogue.

template<int K, int NOUT, int NPAD>
__global__ void __launch_bounds__(256, 2)
gemm_wmma_kernel(const float* __restrict__ A,
                 const __nv_bfloat16* __restrict__ Bh,
                 const __nv_bfloat16* __restrict__ Bl,
                 const float* __restrict__ al, const float* __restrict__ ar,
                 float* __restrict__ Z, int M) {
    constexpr int CH  = K / 64;
    constexpr int NT  = NPAD / 16;
    constexpr int ALD = 136;           // 64 hi + 64 lo + 8 pad
    constexpr int BLD = NPAD + 8;
    constexpr int ABYTES = 128 * ALD * 2;

    __shared__ __align__(16) unsigned char sraw[ABYTES + 128 * BLD * 2];
    __nv_bfloat16 (*As)[ALD] = (__nv_bfloat16(*)[ALD])sraw;
    __nv_bfloat16 (*Bs)[BLD] = (__nv_bfloat16(*)[BLD])(sraw + ABYTES);

    int tid  = threadIdx.x;
    int wid  = tid >> 5;
    int lane = tid & 31;
    int m0   = blockIdx.x * 128;

    // This thread's A-tile slots: 8 float4 per chunk.
    int ar_  = 0, ac_ = 0;  // row / col-base for t computed inline

    wmma::fragment<wmma::accumulator, 16, 16, 16, float> c[NT];
#pragma unroll
    for (int nt = 0; nt < NT; nt++)
        wmma::fill_fragment(c[nt], 0.f);

    // Prefetch chunk 0 into registers.
    float4 pa[8];
#pragma unroll
    for (int t = 0; t < 8; t++) {
        int idx = tid + t * 256;
        int r   = idx >> 4;
        int c4  = (idx & 15) * 4;
        int row = m0 + r;
        pa[t] = make_float4(0.f, 0.f, 0.f, 0.f);
        if (row < M) pa[t] = *(const float4*)&A[(size_t)row * K + c4];
    }
    (void)ar_; (void)ac_;

    for (int ch = 0; ch < CH; ch++) {
        // Store A chunk (convert fp32 -> bf16 hi + residual lo).
#pragma unroll
        for (int t = 0; t < 8; t++) {
            int idx = tid + t * 256;
            int r   = idx >> 4;
            int c4  = (idx & 15) * 4;
            float4 v = pa[t];
            __nv_bfloat16 hx = __float2bfloat16(v.x);
            __nv_bfloat16 hy = __float2bfloat16(v.y);
            __nv_bfloat16 hz = __float2bfloat16(v.z);
            __nv_bfloat16 hw = __float2bfloat16(v.w);
            *(__nv_bfloat162*)&As[r][c4]          = __nv_bfloat162(hx, hy);
            *(__nv_bfloat162*)&As[r][c4 + 2]      = __nv_bfloat162(hz, hw);
            *(__nv_bfloat162*)&As[r][64 + c4]     =
                __floats2bfloat162_rn(v.x - __bfloat162float(hx), v.y - __bfloat162float(hy));
            *(__nv_bfloat162*)&As[r][64 + c4 + 2] =
                __floats2bfloat162_rn(v.z - __bfloat162float(hz), v.w - __bfloat162float(hw));
        }
        // B chunk: hi rows [0,64), lo rows [64,128).
        {
            constexpr int R8 = NPAD / 8;
            int k0 = ch * 64;
            for (int i = tid; i < 64 * R8 * 2; i += 256) {
                int plane = i / (64 * R8);
                int j     = i % (64 * R8);
                int k     = j / R8;
                int b8    = j % R8;
                const __nv_bfloat16* sp = plane ? Bl : Bh;
                uint4 v = *(const uint4*)&sp[(size_t)(k0 + k) * NPAD + b8 * 8];
                *(uint4*)&Bs[plane * 64 + k][b8 * 8] = v;
            }
        }
        __syncthreads();

        // Prefetch next chunk's A while MMAs run.
        if (ch + 1 < CH) {
            int k0n = (ch + 1) * 64;
#pragma unroll
            for (int t = 0; t < 8; t++) {
                int idx = tid + t * 256;
                int r   = idx >> 4;
                int c4  = (idx & 15) * 4;
                int row = m0 + r;
                pa[t] = make_float4(0.f, 0.f, 0.f, 0.f);
                if (row < M) pa[t] = *(const float4*)&A[(size_t)row * K + k0n + c4];
            }
        }

#pragma unroll
        for (int k16 = 0; k16 < 4; k16++) {
            wmma::fragment<wmma::matrix_a, 16, 16, 16, __nv_bfloat16, wmma::row_major> ah, alo;
            wmma::load_matrix_sync(ah,  &As[wid * 16][k16 * 16],      ALD);
            wmma::load_matrix_sync(alo, &As[wid * 16][64 + k16 * 16], ALD);
#pragma unroll
            for (int nt = 0; nt < NT; nt++) {
                wmma::fragment<wmma::matrix_b, 16, 16, 16, __nv_bfloat16, wmma::row_major> bh, bl;
                wmma::load_matrix_sync(bh, &Bs[k16 * 16][nt * 16],      BLD);
                wmma::load_matrix_sync(bl, &Bs[64 + k16 * 16][nt * 16], BLD);
                wmma::mma_sync(c[nt], ah,  bh, c[nt]);
                wmma::mma_sync(c[nt], ah,  bl, c[nt]);
                wmma::mma_sync(c[nt], alo, bh, c[nt]);
            }
        }
        __syncthreads();
    }

    // Epilogue: Cbuf reuses the As region.
    float (*Cbuf)[16][16] = (float(*)[16][16])sraw;
    float (*buf)[16] = Cbuf[wid];
    float el = 0.f, er = 0.f;
    int myrow = m0 + wid * 16 + lane;              // valid for lane < 16

#pragma unroll
    for (int nt = 0; nt < NT; nt++) {
        wmma::store_matrix_sync(&buf[0][0], c[nt], 16, wmma::mem_row_major);
        __syncwarp();
        if (lane < 16 && myrow < M) {
#pragma unroll
            for (int j = 0; j < 16; j++) {
                int col = nt * 16 + j;
                if (col < NOUT) {
                    float v = buf[lane][j];
                    el += v * al[col];
                    er += v * ar[col];
                }
            }
        }
#pragma unroll
        for (int rep = 0; rep < 2; rep++) {
            int idx = lane + rep * 32;
            int r   = idx >> 2;
            int c4  = idx & 3;
            int row = m0 + wid * 16 + r;
            int col = nt * 16 + c4 * 4;
            if (row < M && col < NOUT)
                *(float4*)&Z[(size_t)row * NOUT + col] = *(float4*)&buf[r][c4 * 4];
        }
        __syncwarp();
    }
    if (lane < 16 && myrow < M) { g_el[myrow] = el; g_er[myrow] = er; }
}

// --------------------- fused softmax + aggregation (round-9 best) ----------

__global__ void fused_agg1_kernel(const float* __restrict__ Z, const float* __restrict__ b,
                                  float* __restrict__ H, int n, float neg_slope) {
    int node = (blockIdx.x * blockDim.x + threadIdx.x) >> 5;
    int lane = threadIdx.x & 31;
    if (node >= n) return;
    int start = g_off[node], end = g_off[node + 1];
    int deg   = end - start;
    float erd = g_er[node];

    float aL0 = 0.f, aL1 = 0.f, aH0 = 0.f, aH1 = 0.f, sum = 0.f;

    if (deg <= 32) {
        bool v = lane < deg;
        int   s = v ? g_srcs[start + lane] : 0;
        float e = v ? (g_el[s] + erd) : -3.4e38f;
        e = (e > 0.f) ? e : neg_slope * e;
        float m = warp_max(e);
        float w = v ? expf(e - m) : 0.f;
        sum = w;
        int cnt4 = (deg + 3) & ~3;
        for (int j = 0; j < cnt4; j += 4) {
            int   s0 = __shfl_sync(0xffffffffu, s, j);
            float w0 = __shfl_sync(0xffffffffu, w, j);
            int   s1 = __shfl_sync(0xffffffffu, s, j + 1);
            float w1 = __shfl_sync(0xffffffffu, w, j + 1);
            int   s2 = __shfl_sync(0xffffffffu, s, j + 2);
            float w2 = __shfl_sync(0xffffffffu, w, j + 2);
            int   s3 = __shfl_sync(0xffffffffu, s, j + 3);
            float w3 = __shfl_sync(0xffffffffu, w, j + 3);
            const float* z0 = Z + (long long)s0 * 64;
            const float* z1 = Z + (long long)s1 * 64;
            const float* z2 = Z + (long long)s2 * 64;
            const float* z3 = Z + (long long)s3 * 64;
            aL0 += w0 * z0[lane];  aH0 += w0 * z0[lane + 32];
            aL1 += w1 * z1[lane];  aH1 += w1 * z1[lane + 32];
            aL0 += w2 * z2[lane];  aH0 += w2 * z2[lane + 32];
            aL1 += w3 * z3[lane];  aH1 += w3 * z3[lane + 32];
        }
    } else {
        float m = -3.4e38f;
        for (int i = start + lane; i < end; i += 32) {
            float e = g_el[g_srcs[i]] + erd;
            e = (e > 0.f) ? e : neg_slope * e;
            m = fmaxf(m, e);
        }
        m = warp_max(m);
        for (int c = start; c < end; c += 32) {
            int idx = c + lane;
            bool v = idx < end;
            int   s = v ? g_srcs[idx] : 0;
            float e = v ? (g_el[s] + erd) : -3.4e38f;
            e = (e > 0.f) ? e : neg_slope * e;
            float w = v ? expf(e - m) : 0.f;
            sum += w;
            int cnt  = min(32, end - c);
            int cnt4 = (cnt + 3) & ~3;
            for (int j = 0; j < cnt4; j += 4) {
                int   s0 = __shfl_sync(0xffffffffu, s, j);
                float w0 = __shfl_sync(0xffffffffu, w, j);
                int   s1 = __shfl_sync(0xffffffffu, s, j + 1);
                float w1 = __shfl_sync(0xffffffffu, w, j + 1);
                int   s2 = __shfl_sync(0xffffffffu, s, j + 2);
                float w2 = __shfl_sync(0xffffffffu, w, j + 2);
                int   s3 = __shfl_sync(0xffffffffu, s, j + 3);
                float w3 = __shfl_sync(0xffffffffu, w, j + 3);
                const float* z0 = Z + (long long)s0 * 64;
                const float* z1 = Z + (long long)s1 * 64;
                const float* z2 = Z + (long long)s2 * 64;
                const float* z3 = Z + (long long)s3 * 64;
                aL0 += w0 * z0[lane];  aH0 += w0 * z0[lane + 32];
                aL1 += w1 * z1[lane];  aH1 += w1 * z1[lane + 32];
                aL0 += w2 * z2[lane];  aH0 += w2 * z2[lane + 32];
                aL1 += w3 * z3[lane];  aH1 += w3 * z3[lane + 32];
            }
        }
    }

    sum = warp_sum(sum);
    float sinv = (deg > 0) ? 1.f / sum : 0.f;
    float vL = (aL0 + aL1) * sinv + b[lane];
    float vH = (aH0 + aH1) * sinv + b[lane + 32];
    H[(long long)node * 64 + lane]      = (vL > 0.f) ? vL : 0.f;
    H[(long long)node * 64 + lane + 32] = (vH > 0.f) ? vH : 0.f;
}

__global__ void fused_agg2_kernel(const float* __restrict__ Z, const float* __restrict__ b,
                                  float* __restrict__ out, int n, float neg_slope) {
    int gw   = (blockIdx.x * blockDim.x + threadIdx.x) >> 5;
    int node = gw;
    int lane = threadIdx.x & 31;
    if (node >= n) return;
    int start = g_off[node], end = g_off[node + 1];
    int deg   = end - start;
    float erd = g_er[node];
    bool h1 = lane < 8;

    float accA = 0.f, accB = 0.f, acc1 = 0.f, sum = 0.f;

    if (deg <= 32) {
        bool v = lane < deg;
        int   s = v ? g_srcs[start + lane] : 0;
        float e = v ? (g_el[s] + erd) : -3.4e38f;
        e = (e > 0.f) ? e : neg_slope * e;
        float m = warp_max(e);
        float w = v ? expf(e - m) : 0.f;
        sum = w;
        int cnt8 = (deg + 7) & ~7;
        for (int j = 0; j < cnt8; j += 8) {
#pragma unroll
            for (int jj = 0; jj < 8; jj += 2) {
                int   s0 = __shfl_sync(0xffffffffu, s, j + jj);
                float w0 = __shfl_sync(0xffffffffu, w, j + jj);
                int   s1 = __shfl_sync(0xffffffffu, s, j + jj + 1);
                float w1 = __shfl_sync(0xffffffffu, w, j + jj + 1);
                const float* z0 = Z + (long long)s0 * 40;
                const float* z1 = Z + (long long)s1 * 40;
                accA += w0 * z0[lane];
                accB += w1 * z1[lane];
                if (h1) acc1 += w0 * z0[lane + 32] + w1 * z1[lane + 32];
            }
        }
    } else {
        float m = -3.4e38f;
        for (int i = start + lane; i < end; i += 32) {
            float e = g_el[g_srcs[i]] + erd;
            e = (e > 0.f) ? e : neg_slope * e;
            m = fmaxf(m, e);
        }
        m = warp_max(m);
        for (int c = start; c < end; c += 32) {
            int idx = c + lane;
            bool v = idx < end;
            int   s = v ? g_srcs[idx] : 0;
            float e = v ? (g_el[s] + erd) : -3.4e38f;
            e = (e > 0.f) ? e : neg_slope * e;
            float w = v ? expf(e - m) : 0.f;
            sum += w;
            int cnt  = min(32, end - c);
            int cnt8 = (cnt + 7) & ~7;
            for (int j = 0; j < cnt8; j += 8) {
#pragma unroll
                for (int jj = 0; jj < 8; jj += 2) {
                    int   s0 = __shfl_sync(0xffffffffu, s, j + jj);
                    float w0 = __shfl_sync(0xffffffffu, w, j + jj);
                    int   s1 = __shfl_sync(0xffffffffu, s, j + jj + 1);
                    float w1 = __shfl_sync(0xffffffffu, w, j + jj + 1);
                    const float* z0 = Z + (long long)s0 * 40;
                    const float* z1 = Z + (long long)s1 * 40;
                    accA += w0 * z0[lane];
                    accB += w1 * z1[lane];
                    if (h1) acc1 += w0 * z0[lane + 32] + w1 * z1[lane + 32];
                }
            }
        }
    }

    sum = warp_sum(sum);
    float sinv = (deg > 0) ? 1.f / sum : 0.f;
    float v0 = (accA + accB) * sinv + b[lane];
    float v1 = h1 ? (acc1 * sinv + b[lane + 32]) : -3.4e38f;

    float mx = warp_max(fmaxf(v0, v1));
    float se = warp_sum(expf(v0 - mx) + (h1 ? expf(v1 - mx) : 0.f));
    float lse = mx + logf(se);

    long long base = (long long)node * 40;
    out[base + lane] = v0 - lse;
    if (h1) out[base + lane + 32] = v1 - lse;
}

// ----------------------------- host launch ---------------------------------

extern "C" void kernel_launch(void* const* d_in, const int* in_sizes, int n_in,
                              void* d_out, int out_size) {
    const float* feat = (const float*)d_in[0];
    const int*   src  = (const int*)  d_in[1];
    const int*   dst  = (const int*)  d_in[2];
    const float* W1   = (const float*)d_in[3];
    const float* b1   = (const float*)d_in[4];
    const float* al1  = (const float*)d_in[5];
    const float* ar1  = (const float*)d_in[6];
    const float* W2   = (const float*)d_in[7];
    const float* b2   = (const float*)d_in[8];
    const float* al2  = (const float*)d_in[9];
    const float* ar2  = (const float*)d_in[10];
    float* out = (float*)d_out;

    const int IN = 256;
    int n = in_sizes[0] / IN;   // 100000
    int E = in_sizes[1];        // 1600000

    float* zp; cudaGetSymbolAddress((void**)&zp, g_z);
    float* hp; cudaGetSymbolAddress((void**)&hp, g_h);
    __nv_bfloat16 *bt1h, *bt1l, *bt2h, *bt2l;
    cudaGetSymbolAddress((void**)&bt1h, g_bt1h);
    cudaGetSymbolAddress((void**)&bt1l, g_bt1l);
    cudaGetSymbolAddress((void**)&bt2h, g_bt2h);
    cudaGetSymbolAddress((void**)&bt2l, g_bt2l);

    const float NEG_SLOPE = 0.2f;
    int mb128 = (n + 127) / 128;
    int nb_scan = (n + SCAN_CHUNK - 1) / SCAN_CHUNK;

    // gemm1 at stream launch index 3 (profiler's capture slot).
    wconv_kernel<<<(256 * 64 + 255) / 256, 256>>>(W1, 256, 64, 64, bt1h, bt1l);      // 0
    hist_kernel<<<(E + 255) / 256, 256>>>(dst, E);                                   // 1
    scan_phase1<<<nb_scan, SCAN_CHUNK>>>(n);                                         // 2
    gemm_wmma_kernel<256, 64, 64><<<mb128, 256>>>(feat, bt1h, bt1l, al1, ar1, zp, n);// 3 <- profiled
    wconv_kernel<<<(64 * 48 + 255) / 256, 256>>>(W2, 64, 40, 48, bt2h, bt2l);        // 4
    scan_phase2<<<1, 32>>>(nb_scan);                                                 // 5
    scan_phase3<<<(n + 255) / 256, 256>>>(n);                                        // 6
    scatter_kernel<<<(E + 255) / 256, 256>>>(src, dst, E);                           // 7

    fused_agg1_kernel<<<(n * 32 + 255) / 256, 256>>>(zp, b1, hp, n, NEG_SLOPE);      // 8
    gemm_wmma_kernel<64, 40, 48><<<mb128, 256>>>(hp, bt2h, bt2l, al2, ar2, zp, n);   // 9
    fused_agg2_kernel<<<(n * 32 + 255) / 256, 256>>>(zp, b2, out, n, NEG_SLOPE);     // 10
}

// round 11
// speedup vs baseline: 1.3074x; 1.0462x over previous
#include <cuda_runtime.h>
#include <cuda_bf16.h>
#include <mma.h>
#include <math.h>
#include <stdint.h>

using namespace nvcuda;

// ---------------------------------------------------------------------------
// DenseGAT: 2-layer GAT, N=100000 nodes, E=1600000 edges, 256 -> 64 -> 40
// bf16-split WMMA GEMM (2D warp tile, trunc split, 2 CTAs/SM, A-prefetch)
// + fused logits; CSR-by-dst; round-9 gather aggregation (measured best).
// ---------------------------------------------------------------------------

#define MAX_NODES 100000
#define MAX_EDGES 1600000
#define SCAN_CHUNK 512
#define MAX_BLOCKS_SCAN 256

__device__ float g_z   [MAX_NODES * 64];
__device__ float g_h   [MAX_NODES * 64];
__device__ float g_el  [MAX_NODES];
__device__ float g_er  [MAX_NODES];
__device__ int   g_deg [MAX_NODES];
__device__ int   g_scan[MAX_NODES];
__device__ int   g_off [MAX_NODES + 1];
__device__ int   g_cur [MAX_NODES];
__device__ int   g_srcs[MAX_EDGES];
__device__ int   g_bsum[MAX_BLOCKS_SCAN];
__device__ int   g_boff[MAX_BLOCKS_SCAN];

// bf16 hi/lo W planes, row-major padded: layer1 [256][64], layer2 [64][48]
__device__ __align__(16) __nv_bfloat16 g_bt1h[256 * 64];
__device__ __align__(16) __nv_bfloat16 g_bt1l[256 * 64];
__device__ __align__(16) __nv_bfloat16 g_bt2h[64 * 48];
__device__ __align__(16) __nv_bfloat16 g_bt2l[64 * 48];

__device__ __forceinline__ float warp_max(float v) {
#pragma unroll
    for (int o = 16; o > 0; o >>= 1)
        v = fmaxf(v, __shfl_xor_sync(0xffffffffu, v, o));
    return v;
}
__device__ __forceinline__ float warp_sum(float v) {
#pragma unroll
    for (int o = 16; o > 0; o >>= 1)
        v += __shfl_xor_sync(0xffffffffu, v, o);
    return v;
}

// ----------------------------- W convert ----------------------------------

__global__ void wconv_kernel(const float* __restrict__ W, int K, int NOUT, int NPAD,
                             __nv_bfloat16* __restrict__ oh, __nv_bfloat16* __restrict__ ol) {
    int idx = blockIdx.x * blockDim.x + threadIdx.x;
    if (idx >= K * NPAD) return;
    int k = idx / NPAD;
    int n = idx % NPAD;
    float v = (n < NOUT) ? W[k * NOUT + n] : 0.f;
    __nv_bfloat16 h = __float2bfloat16(v);
    __nv_bfloat16 l = __float2bfloat16(v - __bfloat162float(h));
    oh[idx] = h;
    ol[idx] = l;
}

// ----------------------------- CSR build ----------------------------------

__global__ void hist_kernel(const int* __restrict__ dst, int E) {
    int i = blockIdx.x * blockDim.x + threadIdx.x;
    if (i < E) atomicAdd(&g_deg[dst[i]], 1);
}

__global__ void scan_phase1(int n) {
    __shared__ int sm[SCAN_CHUNK];
    int i = blockIdx.x * SCAN_CHUNK + threadIdx.x;
    int d = (i < n) ? g_deg[i] : 0;
    if (i < n) g_deg[i] = 0;
    sm[threadIdx.x] = d;
    __syncthreads();
#pragma unroll
    for (int o = 1; o < SCAN_CHUNK; o <<= 1) {
        int t = (threadIdx.x >= o) ? sm[threadIdx.x - o] : 0;
        __syncthreads();
        sm[threadIdx.x] += t;
        __syncthreads();
    }
    if (i < n) g_scan[i] = sm[threadIdx.x];
    if (threadIdx.x == SCAN_CHUNK - 1) g_bsum[blockIdx.x] = sm[SCAN_CHUNK - 1];
}

__global__ void scan_phase2(int nb) {
    int lane = threadIdx.x;
    int base = lane * 8;
    int v[8];
    int s = 0;
#pragma unroll
    for (int j = 0; j < 8; j++) {
        int x = (base + j < nb) ? g_bsum[base + j] : 0;
        v[j] = s;
        s += x;
    }
    int t = s;
#pragma unroll
    for (int o = 1; o < 32; o <<= 1) {
        int u = __shfl_up_sync(0xffffffffu, t, o);
        if (lane >= o) t += u;
    }
    int excl = t - s;
#pragma unroll
    for (int j = 0; j < 8; j++)
        if (base + j < nb) g_boff[base + j] = excl + v[j];
}

__global__ void scan_phase3(int n) {
    int i = blockIdx.x * blockDim.x + threadIdx.x;
    if (i < n) {
        int v = g_scan[i] + g_boff[i >> 9];
        g_off[i + 1] = v;
        if (i + 1 < n) g_cur[i + 1] = v;
    }
    if (i == 0) { g_off[0] = 0; g_cur[0] = 0; }
}

__global__ void scatter_kernel(const int* __restrict__ src, const int* __restrict__ dst, int E) {
    int i = blockIdx.x * blockDim.x + threadIdx.x;
    if (i >= E) return;
    int pos = atomicAdd(&g_cur[dst[i]], 1);
    g_srcs[pos] = src[i];
}

// ----------------------------- WMMA GEMM + fused logits --------------------
// 3-term bf16 split: A*W ~= Ah*Bh + Ah*Bl + Al*Bh (fp32 accum).
// A hi = truncated bf16 (bits & 0xFFFF0000), lo = bf16(v - hi).
// 256 threads / 8 warps / 128 rows; K-chunk 64; 2D warp tile (COLW col-warps).
// smem ~53KB, __launch_bounds__(256,2) -> 2 CTAs/SM. A prefetched in regs.

template<int K, int NOUT, int NPAD, int COLW>
__global__ void __launch_bounds__(256, 2)
gemm_wmma_kernel(const float* __restrict__ A,
                 const __nv_bfloat16* __restrict__ Bh,
                 const __nv_bfloat16* __restrict__ Bl,
                 const float* __restrict__ al, const float* __restrict__ ar,
                 float* __restrict__ Z, int M) {
    constexpr int CH  = K / 64;
    constexpr int ROWG = 8 / COLW;        // row-warp groups
    constexpr int RPW  = 128 / ROWG;      // rows per warp
    constexpr int RF   = RPW / 16;        // row fragments per warp
    constexpr int CT   = NPAD / 16 / COLW;// col fragments per warp
    constexpr int CWID = NPAD / COLW;     // cols per col-warp group
    constexpr int ALD = 136;              // 64 hi + 64 lo + 8 pad
    constexpr int BLD = NPAD + 8;
    constexpr int ABYTES = 128 * ALD * 2;

    __shared__ __align__(16) unsigned char sraw[ABYTES + 128 * BLD * 2];
    __nv_bfloat16 (*As)[ALD] = (__nv_bfloat16(*)[ALD])sraw;
    __nv_bfloat16 (*Bs)[BLD] = (__nv_bfloat16(*)[BLD])(sraw + ABYTES);

    int tid  = threadIdx.x;
    int wid  = tid >> 5;
    int lane = tid & 31;
    int m0   = blockIdx.x * 128;
    int cw   = wid % COLW;
    int rw   = wid / COLW;

    wmma::fragment<wmma::accumulator, 16, 16, 16, float> c[RF][CT];
#pragma unroll
    for (int rf = 0; rf < RF; rf++)
#pragma unroll
        for (int ct = 0; ct < CT; ct++)
            wmma::fill_fragment(c[rf][ct], 0.f);

    // Prefetch chunk 0 into registers.
    float4 pa[8];
#pragma unroll
    for (int t = 0; t < 8; t++) {
        int idx = tid + t * 256;
        int r   = idx >> 4;
        int c4  = (idx & 15) * 4;
        int row = m0 + r;
        pa[t] = make_float4(0.f, 0.f, 0.f, 0.f);
        if (row < M) pa[t] = *(const float4*)&A[(size_t)row * K + c4];
    }

    for (int ch = 0; ch < CH; ch++) {
        // Store A chunk: truncation split (LOP3 + PRMT hi, FADD + CVT lo).
#pragma unroll
        for (int t = 0; t < 8; t++) {
            int idx = tid + t * 256;
            int r   = idx >> 4;
            int c4  = (idx & 15) * 4;
            float4 v = pa[t];
            unsigned bx = __float_as_uint(v.x) & 0xFFFF0000u;
            unsigned by = __float_as_uint(v.y) & 0xFFFF0000u;
            unsigned bz = __float_as_uint(v.z) & 0xFFFF0000u;
            unsigned bw = __float_as_uint(v.w) & 0xFFFF0000u;
            unsigned h01 = __byte_perm(__float_as_uint(v.x), __float_as_uint(v.y), 0x7632);
            unsigned h23 = __byte_perm(__float_as_uint(v.z), __float_as_uint(v.w), 0x7632);
            *(unsigned*)&As[r][c4]     = h01;
            *(unsigned*)&As[r][c4 + 2] = h23;
            *(__nv_bfloat162*)&As[r][64 + c4] =
                __floats2bfloat162_rn(v.x - __uint_as_float(bx), v.y - __uint_as_float(by));
            *(__nv_bfloat162*)&As[r][64 + c4 + 2] =
                __floats2bfloat162_rn(v.z - __uint_as_float(bz), v.w - __uint_as_float(bw));
        }
        // B chunk: hi rows [0,64), lo rows [64,128).
        {
            constexpr int R8 = NPAD / 8;
            int k0 = ch * 64;
            for (int i = tid; i < 64 * R8 * 2; i += 256) {
                int plane = i / (64 * R8);
                int j     = i % (64 * R8);
                int k     = j / R8;
                int b8    = j % R8;
                const __nv_bfloat16* sp = plane ? Bl : Bh;
                uint4 v = *(const uint4*)&sp[(size_t)(k0 + k) * NPAD + b8 * 8];
                *(uint4*)&Bs[plane * 64 + k][b8 * 8] = v;
            }
        }
        __syncthreads();

        // Prefetch next chunk's A while MMAs run.
        if (ch + 1 < CH) {
            int k0n = (ch + 1) * 64;
#pragma unroll
            for (int t = 0; t < 8; t++) {
                int idx = tid + t * 256;
                int r   = idx >> 4;
                int c4  = (idx & 15) * 4;
                int row = m0 + r;
                pa[t] = make_float4(0.f, 0.f, 0.f, 0.f);
                if (row < M) pa[t] = *(const float4*)&A[(size_t)row * K + k0n + c4];
            }
        }

#pragma unroll
        for (int k16 = 0; k16 < 4; k16++) {
            wmma::fragment<wmma::matrix_a, 16, 16, 16, __nv_bfloat16, wmma::row_major> ah[RF], alo[RF];
#pragma unroll
            for (int rf = 0; rf < RF; rf++) {
                wmma::load_matrix_sync(ah[rf],  &As[rw * RPW + rf * 16][k16 * 16],      ALD);
                wmma::load_matrix_sync(alo[rf], &As[rw * RPW + rf * 16][64 + k16 * 16], ALD);
            }
#pragma unroll
            for (int ct = 0; ct < CT; ct++) {
                int cb = cw * CWID + ct * 16;
                wmma::fragment<wmma::matrix_b, 16, 16, 16, __nv_bfloat16, wmma::row_major> bh, bl;
                wmma::load_matrix_sync(bh, &Bs[k16 * 16][cb],      BLD);
                wmma::load_matrix_sync(bl, &Bs[64 + k16 * 16][cb], BLD);
#pragma unroll
                for (int rf = 0; rf < RF; rf++) {
                    wmma::mma_sync(c[rf][ct], ah[rf],  bh, c[rf][ct]);
                    wmma::mma_sync(c[rf][ct], ah[rf],  bl, c[rf][ct]);
                    wmma::mma_sync(c[rf][ct], alo[rf], bh, c[rf][ct]);
                }
            }
        }
        __syncthreads();
    }

    // Epilogue: Cbuf reuses As region; el/er reduced across col-warps in smem.
    float (*Cbuf)[16][16] = (float(*)[16][16])sraw;
    float (*buf)[16] = Cbuf[wid];
    float* elbuf = (float*)(sraw + ABYTES);
    float* erbuf = elbuf + 128;
    if (tid < 128) { elbuf[tid] = 0.f; erbuf[tid] = 0.f; }
    __syncthreads();

#pragma unroll
    for (int rf = 0; rf < RF; rf++) {
        float elp = 0.f, erp = 0.f;
#pragma unroll
        for (int ct = 0; ct < CT; ct++) {
            wmma::store_matrix_sync(&buf[0][0], c[rf][ct], 16, wmma::mem_row_major);
            __syncwarp();
            int cb = cw * CWID + ct * 16;
            if (lane < 16) {
                int row = m0 + rw * RPW + rf * 16 + lane;
                if (row < M) {
#pragma unroll
                    for (int j = 0; j < 16; j++) {
                        int col = cb + j;
                        if (col < NOUT) {
                            float v = buf[lane][j];
                            elp += v * al[col];
                            erp += v * ar[col];
                        }
                    }
                }
            }
#pragma unroll
            for (int rep = 0; rep < 2; rep++) {
                int idx = lane + rep * 32;
                int r   = idx >> 2;
                int c4  = idx & 3;
                int row = m0 + rw * RPW + rf * 16 + r;
                int col = cb + c4 * 4;
                if (row < M && col < NOUT)
                    *(float4*)&Z[(size_t)row * NOUT + col] = *(float4*)&buf[r][c4 * 4];
            }
            __syncwarp();
        }
        if (lane < 16) {
            int lrow = rw * RPW + rf * 16 + lane;
            atomicAdd(&elbuf[lrow], elp);
            atomicAdd(&erbuf[lrow], erp);
        }
    }
    __syncthreads();
    if (tid < 128) {
        int row = m0 + tid;
        if (row < M) { g_el[row] = elbuf[tid]; g_er[row] = erbuf[tid]; }
    }
}

// --------------------- fused softmax + aggregation (round-9 best) ----------

__global__ void fused_agg1_kernel(const float* __restrict__ Z, const float* __restrict__ b,
                                  float* __restrict__ H, int n, float neg_slope) {
    int node = (blockIdx.x * blockDim.x + threadIdx.x) >> 5;
    int lane = threadIdx.x & 31;
    if (node >= n) return;
    int start = g_off[node], end = g_off[node + 1];
    int deg   = end - start;
    float erd = g_er[node];

    float aL0 = 0.f, aL1 = 0.f, aH0 = 0.f, aH1 = 0.f, sum = 0.f;

    if (deg <= 32) {
        bool v = lane < deg;
        int   s = v ? g_srcs[start + lane] : 0;
        float e = v ? (g_el[s] + erd) : -3.4e38f;
        e = (e > 0.f) ? e : neg_slope * e;
        float m = warp_max(e);
        float w = v ? expf(e - m) : 0.f;
        sum = w;
        int cnt4 = (deg + 3) & ~3;
        for (int j = 0; j < cnt4; j += 4) {
            int   s0 = __shfl_sync(0xffffffffu, s, j);
            float w0 = __shfl_sync(0xffffffffu, w, j);
            int   s1 = __shfl_sync(0xffffffffu, s, j + 1);
            float w1 = __shfl_sync(0xffffffffu, w, j + 1);
            int   s2 = __shfl_sync(0xffffffffu, s, j + 2);
            float w2 = __shfl_sync(0xffffffffu, w, j + 2);
            int   s3 = __shfl_sync(0xffffffffu, s, j + 3);
            float w3 = __shfl_sync(0xffffffffu, w, j + 3);
            const float* z0 = Z + (long long)s0 * 64;
            const float* z1 = Z + (long long)s1 * 64;
            const float* z2 = Z + (long long)s2 * 64;
            const float* z3 = Z + (long long)s3 * 64;
            aL0 += w0 * z0[lane];  aH0 += w0 * z0[lane + 32];
            aL1 += w1 * z1[lane];  aH1 += w1 * z1[lane + 32];
            aL0 += w2 * z2[lane];  aH0 += w2 * z2[lane + 32];
            aL1 += w3 * z3[lane];  aH1 += w3 * z3[lane + 32];
        }
    } else {
        float m = -3.4e38f;
        for (int i = start + lane; i < end; i += 32) {
            float e = g_el[g_srcs[i]] + erd;
            e = (e > 0.f) ? e : neg_slope * e;
            m = fmaxf(m, e);
        }
        m = warp_max(m);
        for (int c = start; c < end; c += 32) {
            int idx = c + lane;
            bool v = idx < end;
            int   s = v ? g_srcs[idx] : 0;
            float e = v ? (g_el[s] + erd) : -3.4e38f;
            e = (e > 0.f) ? e : neg_slope * e;
            float w = v ? expf(e - m) : 0.f;
            sum += w;
            int cnt  = min(32, end - c);
            int cnt4 = (cnt + 3) & ~3;
            for (int j = 0; j < cnt4; j += 4) {
                int   s0 = __shfl_sync(0xffffffffu, s, j);
                float w0 = __shfl_sync(0xffffffffu, w, j);
                int   s1 = __shfl_sync(0xffffffffu, s, j + 1);
                float w1 = __shfl_sync(0xffffffffu, w, j + 1);
                int   s2 = __shfl_sync(0xffffffffu, s, j + 2);
                float w2 = __shfl_sync(0xffffffffu, w, j + 2);
                int   s3 = __shfl_sync(0xffffffffu, s, j + 3);
                float w3 = __shfl_sync(0xffffffffu, w, j + 3);
                const float* z0 = Z + (long long)s0 * 64;
                const float* z1 = Z + (long long)s1 * 64;
                const float* z2 = Z + (long long)s2 * 64;
                const float* z3 = Z + (long long)s3 * 64;
                aL0 += w0 * z0[lane];  aH0 += w0 * z0[lane + 32];
                aL1 += w1 * z1[lane];  aH1 += w1 * z1[lane + 32];
                aL0 += w2 * z2[lane];  aH0 += w2 * z2[lane + 32];
                aL1 += w3 * z3[lane];  aH1 += w3 * z3[lane + 32];
            }
        }
    }

    sum = warp_sum(sum);
    float sinv = (deg > 0) ? 1.f / sum : 0.f;
    float vL = (aL0 + aL1) * sinv + b[lane];
    float vH = (aH0 + aH1) * sinv + b[lane + 32];
    H[(long long)node * 64 + lane]      = (vL > 0.f) ? vL : 0.f;
    H[(long long)node * 64 + lane + 32] = (vH > 0.f) ? vH : 0.f;
}

__global__ void fused_agg2_kernel(const float* __restrict__ Z, const float* __restrict__ b,
                                  float* __restrict__ out, int n, float neg_slope) {
    int gw   = (blockIdx.x * blockDim.x + threadIdx.x) >> 5;
    int node = gw;
    int lane = threadIdx.x & 31;
    if (node >= n) return;
    int start = g_off[node], end = g_off[node + 1];
    int deg   = end - start;
    float erd = g_er[node];
    bool h1 = lane < 8;

    float accA = 0.f, accB = 0.f, acc1 = 0.f, sum = 0.f;

    if (deg <= 32) {
        bool v = lane < deg;
        int   s = v ? g_srcs[start + lane] : 0;
        float e = v ? (g_el[s] + erd) : -3.4e38f;
        e = (e > 0.f) ? e : neg_slope * e;
        float m = warp_max(e);
        float w = v ? expf(e - m) : 0.f;
        sum = w;
        int cnt8 = (deg + 7) & ~7;
        for (int j = 0; j < cnt8; j += 8) {
#pragma unroll
            for (int jj = 0; jj < 8; jj += 2) {
                int   s0 = __shfl_sync(0xffffffffu, s, j + jj);
                float w0 = __shfl_sync(0xffffffffu, w, j + jj);
                int   s1 = __shfl_sync(0xffffffffu, s, j + jj + 1);
                float w1 = __shfl_sync(0xffffffffu, w, j + jj + 1);
                const float* z0 = Z + (long long)s0 * 40;
                const float* z1 = Z + (long long)s1 * 40;
                accA += w0 * z0[lane];
                accB += w1 * z1[lane];
                if (h1) acc1 += w0 * z0[lane + 32] + w1 * z1[lane + 32];
            }
        }
    } else {
        float m = -3.4e38f;
        for (int i = start + lane; i < end; i += 32) {
            float e = g_el[g_srcs[i]] + erd;
            e = (e > 0.f) ? e : neg_slope * e;
            m = fmaxf(m, e);
        }
        m = warp_max(m);
        for (int c = start; c < end; c += 32) {
            int idx = c + lane;
            bool v = idx < end;
            int   s = v ? g_srcs[idx] : 0;
            float e = v ? (g_el[s] + erd) : -3.4e38f;
            e = (e > 0.f) ? e : neg_slope * e;
            float w = v ? expf(e - m) : 0.f;
            sum += w;
            int cnt  = min(32, end - c);
            int cnt8 = (cnt + 7) & ~7;
            for (int j = 0; j < cnt8; j += 8) {
#pragma unroll
                for (int jj = 0; jj < 8; jj += 2) {
                    int   s0 = __shfl_sync(0xffffffffu, s, j + jj);
                    float w0 = __shfl_sync(0xffffffffu, w, j + jj);
                    int   s1 = __shfl_sync(0xffffffffu, s, j + jj + 1);
                    float w1 = __shfl_sync(0xffffffffu, w, j + jj + 1);
                    const float* z0 = Z + (long long)s0 * 40;
                    const float* z1 = Z + (long long)s1 * 40;
                    accA += w0 * z0[lane];
                    accB += w1 * z1[lane];
                    if (h1) acc1 += w0 * z0[lane + 32] + w1 * z1[lane + 32];
                }
            }
        }
    }

    sum = warp_sum(sum);
    float sinv = (deg > 0) ? 1.f / sum : 0.f;
    float v0 = (accA + accB) * sinv + b[lane];
    float v1 = h1 ? (acc1 * sinv + b[lane + 32]) : -3.4e38f;

    float mx = warp_max(fmaxf(v0, v1));
    float se = warp_sum(expf(v0 - mx) + (h1 ? expf(v1 - mx) : 0.f));
    float lse = mx + logf(se);

    long long base = (long long)node * 40;
    out[base + lane] = v0 - lse;
    if (h1) out[base + lane + 32] = v1 - lse;
}

// ----------------------------- host launch ---------------------------------

extern "C" void kernel_launch(void* const* d_in, const int* in_sizes, int n_in,
                              void* d_out, int out_size) {
    const float* feat = (const float*)d_in[0];
    const int*   src  = (const int*)  d_in[1];
    const int*   dst  = (const int*)  d_in[2];
    const float* W1   = (const float*)d_in[3];
    const float* b1   = (const float*)d_in[4];
    const float* al1  = (const float*)d_in[5];
    const float* ar1  = (const float*)d_in[6];
    const float* W2   = (const float*)d_in[7];
    const float* b2   = (const float*)d_in[8];
    const float* al2  = (const float*)d_in[9];
    const float* ar2  = (const float*)d_in[10];
    float* out = (float*)d_out;

    const int IN = 256;
    int n = in_sizes[0] / IN;   // 100000
    int E = in_sizes[1];        // 1600000

    float* zp; cudaGetSymbolAddress((void**)&zp, g_z);
    float* hp; cudaGetSymbolAddress((void**)&hp, g_h);
    __nv_bfloat16 *bt1h, *bt1l, *bt2h, *bt2l;
    cudaGetSymbolAddress((void**)&bt1h, g_bt1h);
    cudaGetSymbolAddress((void**)&bt1l, g_bt1l);
    cudaGetSymbolAddress((void**)&bt2h, g_bt2h);
    cudaGetSymbolAddress((void**)&bt2l, g_bt2l);

    const float NEG_SLOPE = 0.2f;
    int mb128 = (n + 127) / 128;
    int nb_scan = (n + SCAN_CHUNK - 1) / SCAN_CHUNK;

    // gemm1 at stream launch index 3 (profiler's capture slot).
    wconv_kernel<<<(256 * 64 + 255) / 256, 256>>>(W1, 256, 64, 64, bt1h, bt1l);         // 0
    hist_kernel<<<(E + 255) / 256, 256>>>(dst, E);                                      // 1
    scan_phase1<<<nb_scan, SCAN_CHUNK>>>(n);                                            // 2
    gemm_wmma_kernel<256, 64, 64, 2><<<mb128, 256>>>(feat, bt1h, bt1l, al1, ar1, zp, n);// 3 <- profiled
    wconv_kernel<<<(64 * 48 + 255) / 256, 256>>>(W2, 64, 40, 48, bt2h, bt2l);           // 4
    scan_phase2<<<1, 32>>>(nb_scan);                                                    // 5
    scan_phase3<<<(n + 255) / 256, 256>>>(n);                                           // 6
    scatter_kernel<<<(E + 255) / 256, 256>>>(src, dst, E);                              // 7

    fused_agg1_kernel<<<(n * 32 + 255) / 256, 256>>>(zp, b1, hp, n, NEG_SLOPE);         // 8
    gemm_wmma_kernel<64, 40, 48, 1><<<mb128, 256>>>(hp, bt2h, bt2l, al2, ar2, zp, n);   // 9
    fused_agg2_kernel<<<(n * 32 + 255) / 256, 256>>>(zp, b2, out, n, NEG_SLOPE);        // 10
}